// round 7
// baseline (speedup 1.0000x reference)
#include <cuda_runtime.h>
#include <cuda_bf16.h>
#include <cstdint>
#include <stdint.h>
#include <math.h>

typedef __nv_bfloat16 bf16;

// ---------------- problem constants ----------------
#define TOK   2048          // B*T
#define CDIM  1024          // n_embd
#define HH    16            // heads
#define DH    64            // head dim
#define TT    1024          // seq
#define BB    2             // batch
#define NHID  4096          // expert hidden
#define WIN   256           // window

// dynamic smem sizes for the hgemm core (3 stages, BK=64)
#define ASTG_BYTES (128 * 72 * 2)
#define SMEM_HG(BN) (3 * ASTG_BYTES + 3 * 64 * ((BN) + 8) * 2)

// ---------------- scratch (static device globals; no allocation) ----------------
__device__ float g_xn2  [TOK * CDIM];            // fp32 ln2 output (router)
__device__ float g_scores[32u * 1024u * 1024u];  // [h*2+b][t][s] fp32
__device__ float g_sx   [TOK * NHID];
__device__ float g_glu  [TOK * NHID];
__device__ float g_m    [TOK];
__device__ float g_coef [TOK];
__device__ int   g_eidx [TOK];
__device__ int   g_perm [TOK];
__device__ int   g_cnt  [2];

// bf16 buffers
__device__ bf16 g_xnh  [TOK * CDIM];        // ln1 output
__device__ bf16 g_xn2h [TOK * CDIM];        // ln2 output
__device__ bf16 g_qkvh [TOK * 3072];        // [token][qs|k|v]
__device__ bf16 g_krh  [32 * 64 * 1024];    // [z][d][s] reordered k
__device__ bf16 g_wh   [32u * 1024u * 1024u]; // softmax probs
__device__ bf16 g_oh   [TOK * CDIM];        // attention output (concat heads)
__device__ bf16 g_h1h  [TOK * NHID];
__device__ bf16 g_acth [TOK * NHID];
__device__ bf16 g_Wqkvh[CDIM * 3072];
__device__ bf16 g_wph  [CDIM * CDIM];
__device__ bf16 g_w1h  [2 * CDIM * NHID];
__device__ bf16 g_wsh  [2 * NHID * NHID];
__device__ bf16 g_wgh  [2 * NHID * NHID];
__device__ bf16 g_w2h  [2 * NHID * CDIM];

// ================= bf16 tensor-core GEMM core =================
__device__ __forceinline__ void ldsm4(uint32_t r[4], uint32_t addr) {
    asm volatile("ldmatrix.sync.aligned.m8n8.x4.shared.b16 {%0,%1,%2,%3},[%4];"
        : "=r"(r[0]), "=r"(r[1]), "=r"(r[2]), "=r"(r[3]) : "r"(addr));
}
__device__ __forceinline__ void ldsm4t(uint32_t r[4], uint32_t addr) {
    asm volatile("ldmatrix.sync.aligned.m8n8.x4.trans.shared.b16 {%0,%1,%2,%3},[%4];"
        : "=r"(r[0]), "=r"(r[1]), "=r"(r[2]), "=r"(r[3]) : "r"(addr));
}
__device__ __forceinline__ void mma16816(float d[4], const uint32_t a[4], const uint32_t b[2]) {
    asm volatile("mma.sync.aligned.m16n8k16.row.col.f32.bf16.bf16.f32 "
        "{%0,%1,%2,%3},{%4,%5,%6,%7},{%8,%9},{%0,%1,%2,%3};"
        : "+f"(d[0]), "+f"(d[1]), "+f"(d[2]), "+f"(d[3])
        : "r"(a[0]), "r"(a[1]), "r"(a[2]), "r"(a[3]), "r"(b[0]), "r"(b[1]));
}
__device__ __forceinline__ void cp16(uint32_t dst, const void* src) {
    asm volatile("cp.async.cg.shared.global [%0],[%1],16;" :: "r"(dst), "l"(src));
}

// block tile 128 x BN, BK=64, 3-stage cp.async pipeline, ONE barrier per K-step.
// 256 threads = 8 warps (4m x 2n), warp tile 32 x BN/2.
template<int BN>
__device__ __forceinline__ void hgemm_core2(
    const bf16* __restrict__ A, int lda, const int* __restrict__ gather, int row0,
    const bf16* __restrict__ B, int ldb, int K,
    float (&acc)[2][BN/16][4])
{
    const int BPAD = BN + 8;
    const int JP = BN / 32;
    extern __shared__ __align__(16) bf16 dynsm[];
    const uint32_t ASTG = ASTG_BYTES;                 // 128*72*2
    const uint32_t BSTG = 64 * (uint32_t)BPAD * 2;

    const int tid = threadIdx.x;
    const int lane = tid & 31, warp = tid >> 5;
    const int wm = (warp >> 1) * 32, wn = (warp & 1) * (BN / 2);

    // A loader: row = tid>>1 (0..127), col base = (tid&1)*32; 4 x 16B chunks
    const int ar = tid >> 1, ac = (tid & 1) * 32;
    int ga = gather ? gather[row0 + ar] : (row0 + ar);
    const bf16* pa = A + (size_t)ga * lda + ac;

    // B loader: row = tid>>2 (0..63), col base = (tid&3)*(BN/4); JP x 16B chunks
    const int br = tid >> 2, bc = (tid & 3) * (BN / 4);
    const bf16* pb = B + (size_t)br * ldb + bc;

    uint32_t as_base = (uint32_t)__cvta_generic_to_shared(&dynsm[0]);
    uint32_t bs_base = as_base + 3 * ASTG;

    uint32_t a_dst = as_base + (uint32_t)((ar * 72 + ac) * 2);
    uint32_t b_dst = bs_base + (uint32_t)((br * BPAD + bc) * 2);

    uint32_t aaddr[2], baddr[JP];
    #pragma unroll
    for (int f = 0; f < 2; f++)
        aaddr[f] = as_base + (uint32_t)(((wm + f*16 + (lane & 15)) * 72 + (lane >> 4) * 8) * 2);
    #pragma unroll
    for (int jp = 0; jp < JP; jp++)
        baddr[jp] = bs_base + (uint32_t)((((lane & 7) + ((lane >> 3) & 1) * 8) * BPAD
                                          + wn + jp*16 + (lane >> 4) * 8) * 2);

    const int nsteps = K >> 6;

    // prologue: issue stages 0 and (if present) 1
    #pragma unroll
    for (int s = 0; s < 2; s++) {
        if (s < nsteps) {
            int k0 = s << 6;
            uint32_t ao = s * ASTG, bo = s * BSTG;
            #pragma unroll
            for (int j = 0; j < 4; j++) cp16(a_dst + ao + j*16, pa + k0 + j*8);
            #pragma unroll
            for (int j = 0; j < JP; j++) cp16(b_dst + bo + j*16, pb + (size_t)k0 * ldb + j*8);
            asm volatile("cp.async.commit_group;");
        }
    }

    int cbuf = 0;
    for (int it = 0; it < nsteps; it++) {
        if (it + 1 < nsteps) asm volatile("cp.async.wait_group 1;");
        else                 asm volatile("cp.async.wait_group 0;");
        __syncthreads();   // single barrier: prior compute done + stage `it` visible

        if (it + 2 < nsteps) {
            int s = it + 2;
            int nbuf = cbuf + 2; if (nbuf >= 3) nbuf -= 3;
            int k0 = s << 6;
            uint32_t ao = (uint32_t)nbuf * ASTG, bo = (uint32_t)nbuf * BSTG;
            #pragma unroll
            for (int j = 0; j < 4; j++) cp16(a_dst + ao + j*16, pa + k0 + j*8);
            #pragma unroll
            for (int j = 0; j < JP; j++) cp16(b_dst + bo + j*16, pb + (size_t)k0 * ldb + j*8);
            asm volatile("cp.async.commit_group;");
        }

        uint32_t aof = (uint32_t)cbuf * ASTG, bof = (uint32_t)cbuf * BSTG;
        #pragma unroll
        for (int ks = 0; ks < 4; ks++) {
            uint32_t a[2][4];
            ldsm4(a[0], aaddr[0] + aof + ks * 32);
            ldsm4(a[1], aaddr[1] + aof + ks * 32);
            #pragma unroll
            for (int jp = 0; jp < JP; jp++) {
                uint32_t b[4];
                ldsm4t(b, baddr[jp] + bof + (uint32_t)(ks * 16 * BPAD * 2));
                mma16816(acc[0][2*jp],   a[0], b);
                mma16816(acc[0][2*jp+1], a[0], b + 2);
                mma16816(acc[1][2*jp],   a[1], b);
                mma16816(acc[1][2*jp+1], a[1], b + 2);
            }
        }
        if (++cbuf >= 3) cbuf = 0;
    }
}

// ---------------- weight repack: Wq (summed over q) | Wk | Wv -> bf16 [C x 3072] ----------------
__global__ void k_repack(const float* __restrict__ Wq, const float* __restrict__ Wk,
                         const float* __restrict__ Wv)
{
    int idx = blockIdx.x * blockDim.x + threadIdx.x;
    if (idx >= CDIM * 3072) return;
    int c = idx / 3072, n = idx % 3072;
    float val;
    if (n < 1024) {
        int h = n >> 6, d = n & 63;
        val = Wq[(((size_t)h*2 + 0)*CDIM + c)*DH + d] + Wq[(((size_t)h*2 + 1)*CDIM + c)*DH + d];
    } else if (n < 2048) {
        int m = n - 1024; int h = m >> 6, d = m & 63;
        val = Wk[((size_t)h*CDIM + c)*DH + d];
    } else {
        int m = n - 2048; int h = m >> 6, d = m & 63;
        val = Wv[((size_t)h*CDIM + c)*DH + d];
    }
    g_Wqkvh[idx] = __float2bfloat16(val);
}

// ---------------- fp32 -> bf16 weight conversion (expert weights + Wp) ----------------
__global__ void k_convw(const float* __restrict__ Ew1, const float* __restrict__ Ews,
                        const float* __restrict__ Ewg, const float* __restrict__ Ew2,
                        const float* __restrict__ Wp)
{
    const long long N1 = 2LL * CDIM * NHID;     // 8388608
    const long long NS = 2LL * NHID * NHID;     // 33554432
    const long long NP = (long long)CDIM * CDIM;// 1048576
    long long i = (long long)(blockIdx.x * blockDim.x + threadIdx.x) * 4;
    const float* s; bf16* d; long long off;
    if (i < N1)                    { s = Ew1; d = g_w1h; off = i; }
    else if (i < N1 + NS)          { s = Ews; d = g_wsh; off = i - N1; }
    else if (i < N1 + 2*NS)        { s = Ewg; d = g_wgh; off = i - N1 - NS; }
    else if (i < 2*N1 + 2*NS)      { s = Ew2; d = g_w2h; off = i - N1 - 2*NS; }
    else if (i < 2*N1 + 2*NS + NP) { s = Wp;  d = g_wph; off = i - 2*N1 - 2*NS; }
    else return;
    float4 v = *(const float4*)(s + off);
    __nv_bfloat162* p = (__nv_bfloat162*)(d + off);
    p[0] = __floats2bfloat162_rn(v.x, v.y);
    p[1] = __floats2bfloat162_rn(v.z, v.w);
}

// ---------------- layernorm (ddof=1); dst 0 -> g_xnh (bf16), 1 -> g_xn2 + g_xn2h ----------------
__global__ void __launch_bounds__(256) k_ln(const float* __restrict__ src,
                                            const float* __restrict__ gam,
                                            const float* __restrict__ bet, int dst)
{
    int row = blockIdx.x;
    const float* x = src + (size_t)row * CDIM;
    int tid = threadIdx.x;
    float s = 0.f, ss = 0.f;
    for (int c = tid; c < CDIM; c += 256) { float v = x[c]; s += v; ss += v*v; }
    __shared__ float r0[256], r1[256];
    r0[tid] = s; r1[tid] = ss; __syncthreads();
    for (int o = 128; o > 0; o >>= 1) {
        if (tid < o) { r0[tid] += r0[tid+o]; r1[tid] += r1[tid+o]; }
        __syncthreads();
    }
    float mean = r0[0] * (1.f / CDIM);
    float var  = (r1[0] - CDIM * mean * mean) * (1.f / (CDIM - 1));
    float rstd = rsqrtf(var + 1e-5f);
    for (int c = tid; c < CDIM; c += 256) {
        float v = (x[c] - mean) * rstd * gam[c] + bet[c];
        if (dst) {
            g_xn2[(size_t)row * CDIM + c] = v;
            g_xn2h[(size_t)row * CDIM + c] = __float2bfloat16(v);
        } else {
            g_xnh[(size_t)row * CDIM + c] = __float2bfloat16(v);
        }
    }
}

// ---------------- qkv projection: xnh @ Wqkvh -> g_qkvh (bf16) ----------------
__global__ void __launch_bounds__(256) k_hgemm_qkv()
{
    int bm0 = blockIdx.y * 128, bn0 = blockIdx.x * 128;
    float acc[2][8][4] = {};
    hgemm_core2<128>(g_xnh, CDIM, nullptr, bm0, g_Wqkvh + bn0, 3072, CDIM, acc);
    int lane = threadIdx.x & 31, warp = threadIdx.x >> 5;
    int wm = (warp >> 1) * 32, wn = (warp & 1) * 64;
    int gq = lane >> 2, tig = lane & 3;
    #pragma unroll
    for (int f = 0; f < 2; f++) {
        int r = bm0 + wm + f * 16 + gq;
        #pragma unroll
        for (int j = 0; j < 8; j++) {
            int c = bn0 + wn + j * 8 + tig * 2;
            *(__nv_bfloat162*)&g_qkvh[(size_t)r * 3072 + c] =
                __floats2bfloat162_rn(acc[f][j][0], acc[f][j][1]);
            *(__nv_bfloat162*)&g_qkvh[(size_t)(r + 8) * 3072 + c] =
                __floats2bfloat162_rn(acc[f][j][2], acc[f][j][3]);
        }
    }
}

// ---------------- k reorder (reshape-bug map): g_krh[z][d][s] ----------------
__global__ void k_krep()
{
    int idx = blockIdx.x * blockDim.x + threadIdx.x;   // 32*64*1024
    int z = idx >> 16, rem = idx & 65535;
    int d = rem >> 10, s = rem & 1023;
    int h = z >> 1, b = z & 1;
    g_krh[idx] = g_qkvh[(size_t)(b * TT + 16 * d + (s >> 6)) * 3072 + 1024 + h * 64 + (s & 63)];
}

// ---------------- scores = q @ kr * 0.125 -> fp32 ----------------
__global__ void __launch_bounds__(256) k_hgemm_scores()
{
    int bn0 = blockIdx.x * 128, t0 = blockIdx.y * 128, z = blockIdx.z;
    int h = z >> 1, b = z & 1;
    const bf16* A = g_qkvh + (size_t)b * TT * 3072 + h * 64;
    const bf16* B = g_krh + (size_t)z * 65536 + bn0;
    float acc[2][8][4] = {};
    hgemm_core2<128>(A, 3072, nullptr, t0, B, 1024, 64, acc);
    int lane = threadIdx.x & 31, warp = threadIdx.x >> 5;
    int wm = (warp >> 1) * 32, wn = (warp & 1) * 64;
    int gq = lane >> 2, tig = lane & 3;
    #pragma unroll
    for (int f = 0; f < 2; f++) {
        int r = t0 + wm + f * 16 + gq;
        #pragma unroll
        for (int j = 0; j < 8; j++) {
            int c = bn0 + wn + j * 8 + tig * 2;
            *(float2*)&g_scores[(size_t)(z * TT + r) * TT + c] =
                make_float2(acc[f][j][0] * 0.125f, acc[f][j][1] * 0.125f);
            *(float2*)&g_scores[(size_t)(z * TT + r + 8) * TT + c] =
                make_float2(acc[f][j][2] * 0.125f, acc[f][j][3] * 0.125f);
        }
    }
}

// ---------------- softmax with past-window mask -> bf16 probs ----------------
__global__ void __launch_bounds__(256) k_softmax()
{
    int t = blockIdx.x, z = blockIdx.y;
    const float* row = g_scores + (size_t)(z * TT + t) * TT;
    bf16* rout = g_wh + (size_t)(z * TT + t) * TT;
    int bound = t - (WIN - 1); if (bound < 0) bound = 0;
    int tid = threadIdx.x;
    float v[4]; float mx = -1e30f;
    #pragma unroll
    for (int i = 0; i < 4; i++) {
        int s = tid + i * 256;
        float val = row[s];
        v[i] = (s >= bound) ? val : -1e30f;
        mx = fmaxf(mx, v[i]);
    }
    __shared__ float red[256];
    red[tid] = mx; __syncthreads();
    for (int o = 128; o > 0; o >>= 1) { if (tid < o) red[tid] = fmaxf(red[tid], red[tid+o]); __syncthreads(); }
    mx = red[0]; __syncthreads();
    float sum = 0.f;
    #pragma unroll
    for (int i = 0; i < 4; i++) {
        int s = tid + i * 256;
        v[i] = (s >= bound) ? expf(v[i] - mx) : 0.f;
        sum += v[i];
    }
    red[tid] = sum; __syncthreads();
    for (int o = 128; o > 0; o >>= 1) { if (tid < o) red[tid] += red[tid+o]; __syncthreads(); }
    float inv = 1.f / red[0];
    #pragma unroll
    for (int i = 0; i < 4; i++) rout[tid + i*256] = __float2bfloat16(v[i] * inv);
}

// ---------------- o = w @ v -> g_oh (bf16, concat layout) ----------------
__global__ void __launch_bounds__(256) k_hgemm_o()
{
    int t0 = blockIdx.y * 128, z = blockIdx.z;
    int h = z >> 1, b = z & 1;
    const bf16* A = g_wh + (size_t)z * TT * TT;
    const bf16* B = g_qkvh + (size_t)b * TT * 3072 + 2048 + h * 64;
    float acc[2][4][4] = {};
    hgemm_core2<64>(A, TT, nullptr, t0, B, 3072, TT, acc);
    int lane = threadIdx.x & 31, warp = threadIdx.x >> 5;
    int wm = (warp >> 1) * 32, wn = (warp & 1) * 32;
    int gq = lane >> 2, tig = lane & 3;
    #pragma unroll
    for (int f = 0; f < 2; f++) {
        int r = b * TT + t0 + wm + f * 16 + gq;
        #pragma unroll
        for (int j = 0; j < 4; j++) {
            int c = h * 64 + wn + j * 8 + tig * 2;
            *(__nv_bfloat162*)&g_oh[(size_t)r * CDIM + c] =
                __floats2bfloat162_rn(acc[f][j][0], acc[f][j][1]);
            *(__nv_bfloat162*)&g_oh[(size_t)(r + 8) * CDIM + c] =
                __floats2bfloat162_rn(acc[f][j][2], acc[f][j][3]);
        }
    }
}

// ---------------- x1 = x + o @ Wp + bp -> d_out ----------------
__global__ void __launch_bounds__(256) k_hgemm_wp(const float* __restrict__ x,
                                                  const float* __restrict__ bp,
                                                  float* __restrict__ dout)
{
    int bm0 = blockIdx.y * 128, bn0 = blockIdx.x * 128;
    float acc[2][8][4] = {};
    hgemm_core2<128>(g_oh, CDIM, nullptr, bm0, g_wph + bn0, CDIM, CDIM, acc);
    int lane = threadIdx.x & 31, warp = threadIdx.x >> 5;
    int wm = (warp >> 1) * 32, wn = (warp & 1) * 64;
    int gq = lane >> 2, tig = lane & 3;
    #pragma unroll
    for (int f = 0; f < 2; f++) {
        int r = bm0 + wm + f * 16 + gq;
        #pragma unroll
        for (int j = 0; j < 8; j++) {
            int c = bn0 + wn + j * 8 + tig * 2;
            size_t o0 = (size_t)r * CDIM + c;
            size_t o1 = (size_t)(r + 8) * CDIM + c;
            dout[o0]     = x[o0]     + acc[f][j][0] + bp[c];
            dout[o0 + 1] = x[o0 + 1] + acc[f][j][1] + bp[c + 1];
            dout[o1]     = x[o1]     + acc[f][j][2] + bp[c];
            dout[o1 + 1] = x[o1 + 1] + acc[f][j][3] + bp[c + 1];
        }
    }
}

// ---------------- router: per-token logits, top-1 ----------------
__global__ void __launch_bounds__(256) k_router(const float* __restrict__ Wg,
                                                const float* __restrict__ bg)
{
    int t = blockIdx.x;
    const float* xr = g_xn2 + (size_t)t * CDIM;
    int tid = threadIdx.x;
    float l0 = 0.f, l1 = 0.f;
    for (int c = tid; c < CDIM; c += 256) {
        float xv = xr[c];
        l0 += xv * Wg[c * 2 + 0];
        l1 += xv * Wg[c * 2 + 1];
    }
    __shared__ float r0[256], r1[256];
    r0[tid] = l0; r1[tid] = l1; __syncthreads();
    for (int o = 128; o > 0; o >>= 1) {
        if (tid < o) { r0[tid] += r0[tid+o]; r1[tid] += r1[tid+o]; }
        __syncthreads();
    }
    if (tid == 0) {
        float a = r0[0] + bg[0], b = r1[0] + bg[1];
        int e = (a >= b) ? 0 : 1;
        g_eidx[t] = e;
        g_m[t] = fmaxf(a, b);
    }
}

// ---------------- softmax of top logit over TOKEN dim, per batch ----------------
__global__ void __launch_bounds__(256) k_coef()
{
    int b = blockIdx.x, tid = threadIdx.x;
    __shared__ float red[256];
    float v[4]; float mx = -1e30f;
    #pragma unroll
    for (int i = 0; i < 4; i++) { v[i] = g_m[b * TT + tid + i*256]; mx = fmaxf(mx, v[i]); }
    red[tid] = mx; __syncthreads();
    for (int o = 128; o > 0; o >>= 1) { if (tid < o) red[tid] = fmaxf(red[tid], red[tid+o]); __syncthreads(); }
    mx = red[0]; __syncthreads();
    float sum = 0.f;
    #pragma unroll
    for (int i = 0; i < 4; i++) { v[i] = expf(v[i] - mx); sum += v[i]; }
    red[tid] = sum; __syncthreads();
    for (int o = 128; o > 0; o >>= 1) { if (tid < o) red[tid] += red[tid+o]; __syncthreads(); }
    float inv = 1.f / red[0];
    #pragma unroll
    for (int i = 0; i < 4; i++) g_coef[b * TT + tid + i*256] = v[i] * inv;
}

__global__ void k_zero() { if (threadIdx.x < 2) g_cnt[threadIdx.x] = 0; }

__global__ void k_assign()
{
    int t = blockIdx.x * blockDim.x + threadIdx.x;
    if (t >= TOK) return;
    int e = g_eidx[t];
    int pos = atomicAdd(&g_cnt[e], 1);
    int row = (e == 0) ? pos : (TOK - 1 - pos);
    g_perm[row] = t;
}

// ================= MoE tensor-core GEMMs =================
__global__ void __launch_bounds__(256) k_hgemm_h1(const float* __restrict__ Eb1)
{
    int e = blockIdx.z, bm0 = blockIdx.y * 128, bn0 = blockIdx.x * 128;
    int cnt0 = g_cnt[0];
    if (e == 0 && bm0 >= cnt0) return;
    if (e == 1 && bm0 + 128 <= cnt0) return;
    float acc[2][8][4] = {};
    hgemm_core2<128>(g_xn2h, CDIM, g_perm, bm0, g_w1h + (size_t)e * CDIM * NHID + bn0, NHID, CDIM, acc);

    int lane = threadIdx.x & 31, warp = threadIdx.x >> 5;
    int wm = (warp >> 1) * 32, wn = (warp & 1) * 64;
    int gq = lane >> 2, tig = lane & 3;
    const float* bias = Eb1 + (size_t)e * NHID;
    #pragma unroll
    for (int f = 0; f < 2; f++) {
        int r = bm0 + wm + f * 16 + gq;
        bool v0 = (e == 0) ? (r < cnt0)     : (r >= cnt0);
        bool v1 = (e == 0) ? (r + 8 < cnt0) : (r + 8 >= cnt0);
        #pragma unroll
        for (int j = 0; j < 8; j++) {
            int c = bn0 + wn + j * 8 + tig * 2;
            float b0 = bias[c], b1 = bias[c + 1];
            if (v0) *(__nv_bfloat162*)&g_h1h[(size_t)r * NHID + c] =
                __floats2bfloat162_rn(acc[f][j][0] + b0, acc[f][j][1] + b1);
            if (v1) *(__nv_bfloat162*)&g_h1h[(size_t)(r + 8) * NHID + c] =
                __floats2bfloat162_rn(acc[f][j][2] + b0, acc[f][j][3] + b1);
        }
    }
}

__global__ void __launch_bounds__(256) k_hgemm_ff(const float* __restrict__ bias_all, int which)
{
    int e = blockIdx.z, bm0 = blockIdx.y * 128, bn0 = blockIdx.x * 128;
    int cnt0 = g_cnt[0];
    if (e == 0 && bm0 >= cnt0) return;
    if (e == 1 && bm0 + 128 <= cnt0) return;
    const bf16* W = (which ? g_wgh : g_wsh) + (size_t)e * NHID * NHID + bn0;
    float* out = which ? g_glu : g_sx;
    float acc[2][8][4] = {};
    hgemm_core2<128>(g_h1h, NHID, nullptr, bm0, W, NHID, NHID, acc);

    int lane = threadIdx.x & 31, warp = threadIdx.x >> 5;
    int wm = (warp >> 1) * 32, wn = (warp & 1) * 64;
    int gq = lane >> 2, tig = lane & 3;
    const float* bias = bias_all + (size_t)e * NHID;
    #pragma unroll
    for (int f = 0; f < 2; f++) {
        int r = bm0 + wm + f * 16 + gq;
        bool v0 = (e == 0) ? (r < cnt0)     : (r >= cnt0);
        bool v1 = (e == 0) ? (r + 8 < cnt0) : (r + 8 >= cnt0);
        #pragma unroll
        for (int j = 0; j < 8; j++) {
            int c = bn0 + wn + j * 8 + tig * 2;
            float b0 = bias[c], b1 = bias[c + 1];
            if (v0) *(float2*)&out[(size_t)r * NHID + c] =
                make_float2(acc[f][j][0] + b0, acc[f][j][1] + b1);
            if (v1) *(float2*)&out[(size_t)(r + 8) * NHID + c] =
                make_float2(acc[f][j][2] + b0, acc[f][j][3] + b1);
        }
    }
}

__global__ void k_act(const float* __restrict__ Ebeta)
{
    size_t idx = (size_t)blockIdx.x * blockDim.x + threadIdx.x;
    if (idx >= (size_t)TOK * NHID) return;
    int row = (int)(idx >> 12);
    int e = (row < g_cnt[0]) ? 0 : 1;
    float beta = Ebeta[e];
    float s = g_sx[idx];
    float g = g_glu[idx];
    float sw = s * (1.f / (1.f + expf(-beta * s)));
    g_acth[idx] = __float2bfloat16(sw * g);
}

__global__ void __launch_bounds__(256) k_hgemm_out(const float* __restrict__ Eb2,
                                                   float* __restrict__ dout)
{
    int e = blockIdx.z, bm0 = blockIdx.y * 128, bn0 = blockIdx.x * 128;
    int cnt0 = g_cnt[0];
    if (e == 0 && bm0 >= cnt0) return;
    if (e == 1 && bm0 + 128 <= cnt0) return;
    float acc[2][8][4] = {};
    hgemm_core2<128>(g_acth, NHID, nullptr, bm0, g_w2h + (size_t)e * NHID * CDIM + bn0, CDIM, NHID, acc);

    int lane = threadIdx.x & 31, warp = threadIdx.x >> 5;
    int wm = (warp >> 1) * 32, wn = (warp & 1) * 64;
    int gq = lane >> 2, tig = lane & 3;
    const float* bias = Eb2 + (size_t)e * CDIM;
    #pragma unroll
    for (int f = 0; f < 2; f++) {
        int r = bm0 + wm + f * 16 + gq;
        bool v0 = (e == 0) ? (r < cnt0)     : (r >= cnt0);
        bool v1 = (e == 0) ? (r + 8 < cnt0) : (r + 8 >= cnt0);
        int tok0 = v0 ? g_perm[r]     : 0;
        int tok1 = v1 ? g_perm[r + 8] : 0;
        float cf0 = v0 ? g_coef[tok0] : 0.f;
        float cf1 = v1 ? g_coef[tok1] : 0.f;
        #pragma unroll
        for (int j = 0; j < 8; j++) {
            int c = bn0 + wn + j * 8 + tig * 2;
            float b0 = bias[c], b1 = bias[c + 1];
            if (v0) {
                size_t o = (size_t)tok0 * CDIM + c;
                dout[o]     += cf0 * (acc[f][j][0] + b0);
                dout[o + 1] += cf0 * (acc[f][j][1] + b1);
            }
            if (v1) {
                size_t o = (size_t)tok1 * CDIM + c;
                dout[o]     += cf1 * (acc[f][j][2] + b0);
                dout[o + 1] += cf1 * (acc[f][j][3] + b1);
            }
        }
    }
}

// ---------------- launch ----------------
extern "C" void kernel_launch(void* const* d_in, const int* in_sizes, int n_in,
                              void* d_out, int out_size)
{
    const float* x     = (const float*)d_in[0];
    const float* Wq    = (const float*)d_in[1];
    const float* Wk    = (const float*)d_in[2];
    const float* Wv    = (const float*)d_in[3];
    const float* Wp    = (const float*)d_in[4];
    const float* bp    = (const float*)d_in[5];
    const float* ln1g  = (const float*)d_in[6];
    const float* ln1b  = (const float*)d_in[7];
    const float* ln2g  = (const float*)d_in[8];
    const float* ln2b  = (const float*)d_in[9];
    const float* Wg    = (const float*)d_in[10];
    const float* bg    = (const float*)d_in[11];
    const float* Ew1   = (const float*)d_in[12];
    const float* Eb1   = (const float*)d_in[13];
    const float* Ews   = (const float*)d_in[14];
    const float* Ebs   = (const float*)d_in[15];
    const float* Ebeta = (const float*)d_in[16];
    const float* Ewg   = (const float*)d_in[17];
    const float* Ebg   = (const float*)d_in[18];
    const float* Ew2   = (const float*)d_in[19];
    const float* Eb2   = (const float*)d_in[20];
    float* dout = (float*)d_out;

    const int S128 = SMEM_HG(128);   // 107,520 B
    const int S64  = SMEM_HG(64);    //  82,944 B
    cudaFuncSetAttribute(k_hgemm_qkv,    cudaFuncAttributeMaxDynamicSharedMemorySize, S128);
    cudaFuncSetAttribute(k_hgemm_scores, cudaFuncAttributeMaxDynamicSharedMemorySize, S128);
    cudaFuncSetAttribute(k_hgemm_o,      cudaFuncAttributeMaxDynamicSharedMemorySize, S64);
    cudaFuncSetAttribute(k_hgemm_wp,     cudaFuncAttributeMaxDynamicSharedMemorySize, S128);
    cudaFuncSetAttribute(k_hgemm_h1,     cudaFuncAttributeMaxDynamicSharedMemorySize, S128);
    cudaFuncSetAttribute(k_hgemm_ff,     cudaFuncAttributeMaxDynamicSharedMemorySize, S128);
    cudaFuncSetAttribute(k_hgemm_out,    cudaFuncAttributeMaxDynamicSharedMemorySize, S128);

    // weight conversions
    k_convw<<<82944, 256>>>(Ew1, Ews, Ewg, Ew2, Wp);
    k_repack<<<(CDIM * 3072 + 255) / 256, 256>>>(Wq, Wk, Wv);

    // attention (bf16 tensor cores, fp32 accumulate)
    k_ln<<<TOK, 256>>>(x, ln1g, ln1b, 0);
    k_hgemm_qkv<<<dim3(24, 16), 256, S128>>>();
    k_krep<<<8192, 256>>>();
    k_hgemm_scores<<<dim3(8, 8, 32), 256, S128>>>();
    k_softmax<<<dim3(1024, 32), 256>>>();
    k_hgemm_o<<<dim3(1, 8, 32), 256, S64>>>();
    k_hgemm_wp<<<dim3(8, 16), 256, S128>>>(x, bp, dout);

    // MoE routing
    k_ln<<<TOK, 256>>>(dout, ln2g, ln2b, 1);
    k_router<<<TOK, 256>>>(Wg, bg);
    k_coef<<<2, 256>>>();
    k_zero<<<1, 32>>>();
    k_assign<<<8, 256>>>();

    // MoE expert GEMMs (bf16 tensor cores)
    k_hgemm_h1<<<dim3(32, 16, 2), 256, S128>>>(Eb1);
    k_hgemm_ff<<<dim3(32, 16, 2), 256, S128>>>(Ebs, 0);
    k_hgemm_ff<<<dim3(32, 16, 2), 256, S128>>>(Ebg, 1);
    k_act<<<(TOK * NHID + 255) / 256, 256>>>(Ebeta);
    k_hgemm_out<<<dim3(8, 16, 2), 256, S128>>>(Eb2, dout);
}